// round 10
// baseline (speedup 1.0000x reference)
#include <cuda_runtime.h>
#include <cuda_bf16.h>

// Problem-fixed capacities (N=100000, E=1600000 per setup_inputs)
#define NMAX   100000
#define EMAX   1600000
#define ETOTMX (NMAX + EMAX)
#define EPS    1e-16f
#define SCAN_BLK 256
#define NSCANBLK ((NMAX + SCAN_BLK - 1) / SCAN_BLK)   // 391

// ---------------- scratch (static device globals; no allocation) -------------
// NOTE: g_deg relies on zero-init at module load; k_l2fc re-zeroes it at the
// end of every call, so the precondition holds for every (replayed) launch.
__device__ __align__(16) float g_as1 [NMAX * 4];
__device__ __align__(16) float g_ad1 [NMAX * 4];
__device__ __align__(16) float g_h2  [NMAX * 64];   // fp32 (fp16 fails rel-err: R9)
__device__ __align__(16) float g_as2 [NMAX * 8];
__device__ __align__(16) float g_ad2 [NMAX * 8];
__device__ int g_deg [NMAX];
__device__ int g_off [NMAX];
__device__ int g_cur [NMAX];
__device__ int g_csr [ETOTMX];     // src ids grouped by dst
__device__ int g_bsum[NSCANBLK];

__device__ __forceinline__ float lrelu(float t) { return t > 0.f ? t : 0.2f * t; }
__device__ __forceinline__ float elu(float t)   { return t > 0.f ? t : expm1f(t); }

// ---------------- layer 1 node coeffs + dst histogram (fused) ----------------
__global__ void k_l1n_hist(const float* __restrict__ x, const int* __restrict__ dst,
                           const float* __restrict__ W1,
                           const float* __restrict__ atts, const float* __restrict__ attd,
                           int N, int E) {
    int i = blockIdx.x * blockDim.x + threadIdx.x;
    if (i < E) atomicAdd(&g_deg[dst[i]], 1);
    if (i < N) {
        float xv = x[i];
        float4 vs, vd;
        float* ps = &vs.x;
        float* pd = &vd.x;
#pragma unroll
        for (int hd = 0; hd < 4; hd++) {
            float cs = 0.f, cd = 0.f;
#pragma unroll
            for (int c = 0; c < 8; c++) {
                float w = __ldg(&W1[hd * 8 + c]);
                cs += w * __ldg(&atts[hd * 8 + c]);
                cd += w * __ldg(&attd[hd * 8 + c]);
            }
            ps[hd] = xv * cs;
            pd[hd] = xv * cd;
        }
        *(float4*)&g_as1[i * 4] = vs;
        *(float4*)&g_ad1[i * 4] = vd;
    }
}

// ---------------- CSR build: warp-shuffle scans (deg+1: analytic self loop) ---
__global__ void k_scanA(int N) {
    __shared__ int ws[8];
    int t = threadIdx.x, lane = t & 31, warp = t >> 5;
    int i = blockIdx.x * SCAN_BLK + t;
    int v0 = (i < N) ? g_deg[i] + 1 : 0;
    int v = v0;
#pragma unroll
    for (int o = 1; o < 32; o <<= 1) {
        int n = __shfl_up_sync(0xffffffffu, v, o);
        if (lane >= o) v += n;
    }
    if (lane == 31) ws[warp] = v;
    __syncthreads();
    if (t < 8) {
        int w = ws[t];
#pragma unroll
        for (int o = 1; o < 8; o <<= 1) {
            int n = __shfl_up_sync(0xffu, w, o);
            if (t >= o) w += n;
        }
        ws[t] = w;
    }
    __syncthreads();
    int add = warp ? ws[warp - 1] : 0;
    if (i < N) g_off[i] = v + add - v0;                    // exclusive in-block
    if (t == SCAN_BLK - 1) g_bsum[blockIdx.x] = v + add;   // block total
}

__global__ void k_scanB() {
    __shared__ int ws[16];
    int t = threadIdx.x, lane = t & 31, warp = t >> 5;
    int v0 = (t < NSCANBLK) ? g_bsum[t] : 0;
    int v = v0;
#pragma unroll
    for (int o = 1; o < 32; o <<= 1) {
        int n = __shfl_up_sync(0xffffffffu, v, o);
        if (lane >= o) v += n;
    }
    if (lane == 31) ws[warp] = v;
    __syncthreads();
    if (t < 16) {
        int w = ws[t];
#pragma unroll
        for (int o = 1; o < 16; o <<= 1) {
            int n = __shfl_up_sync(0xffffu, w, o);
            if (t >= o) w += n;
        }
        ws[t] = w;
    }
    __syncthreads();
    int add = warp ? ws[warp - 1] : 0;
    if (t < NSCANBLK) g_bsum[t] = v + add - v0;            // exclusive
}

__global__ void k_scanC(int N) {
    int i = blockIdx.x * blockDim.x + threadIdx.x;
    if (i >= N) return;
    int o = g_off[i] + g_bsum[i / SCAN_BLK];
    g_off[i] = o;
    g_cur[i] = o;
    g_deg[i] += 1;                 // include self loop for the gather kernels
}

// ---------------- CSR build: fill ---------------------------------------------
__global__ void k_fill(const int* __restrict__ src, const int* __restrict__ dst,
                       int E, int Etot) {
    int e = blockIdx.x * blockDim.x + threadIdx.x;
    if (e >= Etot) return;
    int s, d;
    if (e < E) { s = src[e]; d = dst[e]; } else { s = d = e - E; }
    int pos = atomicAdd(&g_cur[d], 1);
    g_csr[pos] = s;
}

// ---------------- fused L1 gather + mid phase (warp per node) ------------------
// Phase A: softmax-gather (rank-1 layer 1) -> base per head
// Phase B: act=elu(base*W1+b1) (lane=k), GEMV 32x64 (lane = col-pair),
//          h2 stored fp32, as2/ad2 head dots.
__global__ __launch_bounds__(256) void k_l1mid(const float* __restrict__ x,
                                               const float* __restrict__ W1,
                                               const float* __restrict__ b1,
                                               const float* __restrict__ W2,
                                               const float* __restrict__ atts2,
                                               const float* __restrict__ attd2,
                                               int N) {
    __shared__ float sW1[32], sB1[32], sAs[64], sAd[64];
    __shared__ __align__(16) float2 sW2[32 * 32];   // [k*32+l] = W2[k][2l..2l+1]
    int t = threadIdx.x;
    if (t < 32) { sW1[t] = W1[t]; sB1[t] = b1[t]; }
    if (t >= 64 && t < 128) { sAs[t - 64] = atts2[t - 64]; }
    if (t >= 128 && t < 192) { sAd[t - 128] = attd2[t - 128]; }
    for (int j = t; j < 32 * 32; j += blockDim.x)
        sW2[j] = ((const float2*)W2)[j];
    __syncthreads();

    int gw = (blockIdx.x * blockDim.x + t) >> 5;
    if (gw >= N) return;
    int lane = t & 31;

    // ---- phase A: gather (8 edge slots x 4 heads) ----
    int slot = lane >> 2, hd4 = lane & 3;
    int start = g_off[gw], deg = g_deg[gw];
    float ad = g_ad1[gw * 4 + hd4];
    float psum = 0.f, tsum = 0.f;
    for (int k = slot; k < deg; k += 8) {
        int s = __ldg(&g_csr[start + k]);
        float as = __ldg(&g_as1[s * 4 + hd4]);
        float p = __expf(lrelu(as + ad));
        psum += p;
        tsum += p * __ldg(&x[s]);
    }
#pragma unroll
    for (int o = 4; o < 32; o <<= 1) {
        psum += __shfl_xor_sync(0xffffffffu, psum, o);
        tsum += __shfl_xor_sync(0xffffffffu, tsum, o);
    }
    float base = tsum / (psum + EPS);          // lane holds head (lane&3)

    // ---- phase A2: act[k] for k = lane (head = lane>>3) ----
    float bk = __shfl_sync(0xffffffffu, base, lane >> 3);  // lanes 0..3 hold heads 0..3
    float act = elu(bk * sW1[lane] + sB1[lane]);

    // ---- phase B: GEMV, lane computes cols {2*lane, 2*lane+1} ----
    float2 acc = make_float2(0.f, 0.f);
#pragma unroll
    for (int k = 0; k < 32; k++) {
        float a = __shfl_sync(0xffffffffu, act, k);
        float2 w = sW2[k * 32 + lane];
        acc.x += a * w.x;
        acc.y += a * w.y;
    }
    // store h2 fp32 (coalesced 256B per warp)
    *(float2*)&g_h2[gw * 64 + lane * 2] = acc;

    // head dots: head = lane>>2 spans lanes 4h..4h+3
    float cs = acc.x * sAs[2 * lane] + acc.y * sAs[2 * lane + 1];
    float cd = acc.x * sAd[2 * lane] + acc.y * sAd[2 * lane + 1];
#pragma unroll
    for (int o = 1; o < 4; o <<= 1) {
        cs += __shfl_xor_sync(0xffffffffu, cs, o);
        cd += __shfl_xor_sync(0xffffffffu, cd, o);
    }
    if ((lane & 3) == 0) {
        g_as2[gw * 8 + (lane >> 2)] = cs;
        g_ad2[gw * 8 + (lane >> 2)] = cd;
    }
}

// ---------------- layer 2 gather + finalize + FC (warp per node) --------------
// lanes: slot = lane>>4 (2 edge slots), q = lane&15 -> channels q*4..q*4+3, head q>>1
__global__ void k_l2fc(const float* __restrict__ b2, const float* __restrict__ fcw,
                       const float* __restrict__ fcb, float* __restrict__ out, int N) {
    int gw = (blockIdx.x * blockDim.x + threadIdx.x) >> 5;
    if (gw >= N) return;
    int lane = threadIdx.x & 31;
    int slot = lane >> 4;
    int q = lane & 15;
    int ch = q * 4, hd = q >> 1;
    int start = g_off[gw], deg = g_deg[gw];
    float ad = g_ad2[gw * 8 + hd];
    float4 acc = make_float4(0.f, 0.f, 0.f, 0.f);
    float psum = 0.f;
    for (int k = slot; k < deg; k += 2) {
        int s = __ldg(&g_csr[start + k]);
        float as = __ldg(&g_as2[s * 8 + hd]);
        float p = __expf(lrelu(as + ad));
        float4 h = __ldg((const float4*)&g_h2[s * 64 + ch]);
        acc.x += p * h.x; acc.y += p * h.y;
        acc.z += p * h.z; acc.w += p * h.w;
        psum += p;
    }
    // combine the two edge slots (lanes differing in bit 4)
    acc.x += __shfl_xor_sync(0xffffffffu, acc.x, 16);
    acc.y += __shfl_xor_sync(0xffffffffu, acc.y, 16);
    acc.z += __shfl_xor_sync(0xffffffffu, acc.z, 16);
    acc.w += __shfl_xor_sync(0xffffffffu, acc.w, 16);
    psum  += __shfl_xor_sync(0xffffffffu, psum, 16);
    float inv = 1.f / (psum + EPS);
    float e0 = elu(acc.x * inv + __ldg(&b2[ch]));
    float e1 = elu(acc.y * inv + __ldg(&b2[ch + 1]));
    float e2 = elu(acc.z * inv + __ldg(&b2[ch + 2]));
    float e3 = elu(acc.w * inv + __ldg(&b2[ch + 3]));
    float part = e0 * __ldg(&fcw[ch])     + e1 * __ldg(&fcw[ch + 1])
               + e2 * __ldg(&fcw[ch + 2]) + e3 * __ldg(&fcw[ch + 3]);
    // reduce over the 16 channel-lanes (both halves hold identical data)
#pragma unroll
    for (int o = 8; o > 0; o >>= 1)
        part += __shfl_xor_sync(0xffffffffu, part, o);
    if (lane == 0) {
        out[gw] = part + __ldg(&fcb[0]);
        g_deg[gw] = 0;             // restore zero precondition for next call
    }
}

// ---------------- launch ------------------------------------------------------
extern "C" void kernel_launch(void* const* d_in, const int* in_sizes, int n_in,
                              void* d_out, int out_size) {
    const float* x    = (const float*)d_in[0];
    const int*   ei   = (const int*)  d_in[1];
    const float* W1   = (const float*)d_in[2];
    const float* as1  = (const float*)d_in[3];
    const float* ad1  = (const float*)d_in[4];
    const float* b1   = (const float*)d_in[5];
    const float* W2   = (const float*)d_in[6];
    const float* as2  = (const float*)d_in[7];
    const float* ad2  = (const float*)d_in[8];
    const float* b2   = (const float*)d_in[9];
    const float* fcw  = (const float*)d_in[10];
    const float* fcb  = (const float*)d_in[11];
    float* out = (float*)d_out;

    int N = in_sizes[0];          // x is [N, 1]
    int E = in_sizes[1] / 2;      // edge_index is [2, E]
    int Etot = E + N;             // + self loops
    const int* src = ei;
    const int* dst = ei + E;

    const int T = 256;
    k_l1n_hist<<<(E + T - 1) / T, T>>>(x, dst, W1, as1, ad1, N, E);
    k_scanA   <<<NSCANBLK, SCAN_BLK>>>(N);
    k_scanB   <<<1, 512>>>();
    k_scanC   <<<(N + T - 1) / T, T>>>(N);
    k_fill    <<<(Etot + T - 1) / T, T>>>(src, dst, E, Etot);
    k_l1mid   <<<(int)(((long)N * 32 + T - 1) / T), T>>>(x, W1, b1, W2, as2, ad2, N);
    k_l2fc    <<<(int)(((long)N * 32 + T - 1) / T), T>>>(b2, fcw, fcb, out, N);
}

// round 12
// speedup vs baseline: 1.0553x; 1.0553x over previous
#include <cuda_runtime.h>
#include <cuda_bf16.h>

// Problem-fixed capacities (N=100000, E=1600000 per setup_inputs)
// R12 resubmit of R11 source (two broker-side container failures, no kernel signal).
#define NMAX   100000
#define EMAX   1600000
#define ETOTMX (NMAX + EMAX)
#define EPS    1e-16f
#define SCAN_BLK 256
#define NSCANBLK ((NMAX + SCAN_BLK - 1) / SCAN_BLK)   // 391

// ---------------- scratch (static device globals; no allocation) -------------
// NOTE: g_deg relies on zero-init at module load; k_l2fc re-zeroes it at the
// end of every call, so the precondition holds for every (replayed) launch.
__device__ __align__(16) float g_as1 [NMAX * 4];
__device__ __align__(16) float g_ad1 [NMAX * 4];
__device__ __align__(16) float g_base[NMAX * 4];   // t1/(s1+eps) per head
__device__ __align__(16) float g_h2  [NMAX * 64];  // fp32 (fp16 fails rel-err: R9)
__device__ __align__(16) float g_as2 [NMAX * 8];
__device__ __align__(16) float g_ad2 [NMAX * 8];
__device__ int g_deg [NMAX];
__device__ int g_off [NMAX];
__device__ int g_cur [NMAX];
__device__ int g_csr [ETOTMX];     // src ids grouped by dst
__device__ int g_bsum[NSCANBLK];

__device__ __forceinline__ float lrelu(float t) { return t > 0.f ? t : 0.2f * t; }
__device__ __forceinline__ float elu(float t)   { return t > 0.f ? t : expm1f(t); }

// ---------------- layer 1 node coeffs + dst histogram (fused) ----------------
__global__ void k_l1n_hist(const float* __restrict__ x, const int* __restrict__ dst,
                           const float* __restrict__ W1,
                           const float* __restrict__ atts, const float* __restrict__ attd,
                           int N, int E) {
    int i = blockIdx.x * blockDim.x + threadIdx.x;
    if (i < E) atomicAdd(&g_deg[dst[i]], 1);
    if (i < N) {
        float xv = x[i];
        float4 vs, vd;
        float* ps = &vs.x;
        float* pd = &vd.x;
#pragma unroll
        for (int hd = 0; hd < 4; hd++) {
            float cs = 0.f, cd = 0.f;
#pragma unroll
            for (int c = 0; c < 8; c++) {
                float w = __ldg(&W1[hd * 8 + c]);
                cs += w * __ldg(&atts[hd * 8 + c]);
                cd += w * __ldg(&attd[hd * 8 + c]);
            }
            ps[hd] = xv * cs;
            pd[hd] = xv * cd;
        }
        *(float4*)&g_as1[i * 4] = vs;
        *(float4*)&g_ad1[i * 4] = vd;
    }
}

// ---------------- CSR build: warp-shuffle scans (deg+1: analytic self loop) ---
__global__ void k_scanA(int N) {
    __shared__ int ws[8];
    int t = threadIdx.x, lane = t & 31, warp = t >> 5;
    int i = blockIdx.x * SCAN_BLK + t;
    int v0 = (i < N) ? g_deg[i] + 1 : 0;
    int v = v0;
#pragma unroll
    for (int o = 1; o < 32; o <<= 1) {
        int n = __shfl_up_sync(0xffffffffu, v, o);
        if (lane >= o) v += n;
    }
    if (lane == 31) ws[warp] = v;
    __syncthreads();
    if (t < 8) {
        int w = ws[t];
#pragma unroll
        for (int o = 1; o < 8; o <<= 1) {
            int n = __shfl_up_sync(0xffu, w, o);
            if (t >= o) w += n;
        }
        ws[t] = w;
    }
    __syncthreads();
    int add = warp ? ws[warp - 1] : 0;
    if (i < N) g_off[i] = v + add - v0;                    // exclusive in-block
    if (t == SCAN_BLK - 1) g_bsum[blockIdx.x] = v + add;   // block total
}

__global__ void k_scanB() {
    __shared__ int ws[16];
    int t = threadIdx.x, lane = t & 31, warp = t >> 5;
    int v0 = (t < NSCANBLK) ? g_bsum[t] : 0;
    int v = v0;
#pragma unroll
    for (int o = 1; o < 32; o <<= 1) {
        int n = __shfl_up_sync(0xffffffffu, v, o);
        if (lane >= o) v += n;
    }
    if (lane == 31) ws[warp] = v;
    __syncthreads();
    if (t < 16) {
        int w = ws[t];
#pragma unroll
        for (int o = 1; o < 16; o <<= 1) {
            int n = __shfl_up_sync(0xffffu, w, o);
            if (t >= o) w += n;
        }
        ws[t] = w;
    }
    __syncthreads();
    int add = warp ? ws[warp - 1] : 0;
    if (t < NSCANBLK) g_bsum[t] = v + add - v0;            // exclusive
}

__global__ void k_scanC(int N) {
    int i = blockIdx.x * blockDim.x + threadIdx.x;
    if (i >= N) return;
    int o = g_off[i] + g_bsum[i / SCAN_BLK];
    g_off[i] = o;
    g_cur[i] = o;
    g_deg[i] += 1;                 // include self loop for the gather kernels
}

// ---------------- CSR build: fill ---------------------------------------------
__global__ void k_fill(const int* __restrict__ src, const int* __restrict__ dst,
                       int E, int Etot) {
    int e = blockIdx.x * blockDim.x + threadIdx.x;
    if (e >= Etot) return;
    int s, d;
    if (e < E) { s = src[e]; d = dst[e]; } else { s = d = e - E; }
    int pos = atomicAdd(&g_cur[d], 1);
    g_csr[pos] = s;
}

// ---------------- layer 1: gather-only aggregation (warp per node) ------------
// lanes: slot = lane>>2 (8 edge slots), hd = lane&3
__global__ void k_l1_gather(const float* __restrict__ x, int N) {
    int gw = (blockIdx.x * blockDim.x + threadIdx.x) >> 5;
    if (gw >= N) return;
    int lane = threadIdx.x & 31;
    int slot = lane >> 2, hd = lane & 3;
    int start = g_off[gw], deg = g_deg[gw];
    float ad = g_ad1[gw * 4 + hd];
    float psum = 0.f, tsum = 0.f;
    for (int k = slot; k < deg; k += 8) {
        int s = __ldg(&g_csr[start + k]);
        float as = __ldg(&g_as1[s * 4 + hd]);
        float p = __expf(lrelu(as + ad));
        psum += p;
        tsum += p * __ldg(&x[s]);
    }
#pragma unroll
    for (int o = 4; o < 32; o <<= 1) {
        psum += __shfl_xor_sync(0xffffffffu, psum, o);
        tsum += __shfl_xor_sync(0xffffffffu, tsum, o);
    }
    if (lane < 4) g_base[gw * 4 + hd] = tsum / (psum + EPS);
}

// ---------------- mid phase: one THREAD per node (proven fast shape, R8) ------
// act1 = elu(base * W1 + b1); h2 = act1 @ W2; as2/ad2 = head dots.
__global__ __launch_bounds__(128) void k_mid(const float* __restrict__ W1,
                                             const float* __restrict__ b1,
                                             const float* __restrict__ W2,
                                             const float* __restrict__ atts,
                                             const float* __restrict__ attd,
                                             int N) {
    __shared__ float sW1[32], sB1[32], sAs[64], sAd[64];
    __shared__ __align__(16) float sW2[32 * 64];
    for (int j = threadIdx.x; j < 32; j += blockDim.x) { sW1[j] = W1[j]; sB1[j] = b1[j]; }
    for (int j = threadIdx.x; j < 64; j += blockDim.x) { sAs[j] = atts[j]; sAd[j] = attd[j]; }
    for (int j = threadIdx.x; j < 32 * 64 / 4; j += blockDim.x)
        ((float4*)sW2)[j] = ((const float4*)W2)[j];
    __syncthreads();

    int i = blockIdx.x * blockDim.x + threadIdx.x;
    if (i >= N) return;

    float4 b4 = *(const float4*)&g_base[i * 4];
    const float* bp = &b4.x;
    float act[32];
#pragma unroll
    for (int hd = 0; hd < 4; hd++) {
        float base = bp[hd];
#pragma unroll
        for (int c = 0; c < 8; c++)
            act[hd * 8 + c] = elu(base * sW1[hd * 8 + c] + sB1[hd * 8 + c]);
    }

    float4 as2v[2], ad2v[2];
#pragma unroll
    for (int half = 0; half < 2; half++) {
        float4 acc[8];
#pragma unroll
        for (int j = 0; j < 8; j++) acc[j] = make_float4(0.f, 0.f, 0.f, 0.f);
#pragma unroll
        for (int k = 0; k < 32; k++) {
            float a = act[k];
            const float4* wrow = (const float4*)&sW2[k * 64 + half * 32];
#pragma unroll
            for (int j = 0; j < 8; j++) {
                float4 w = wrow[j];
                acc[j].x += a * w.x; acc[j].y += a * w.y;
                acc[j].z += a * w.z; acc[j].w += a * w.w;
            }
        }
        float* accf = (float*)acc;
#pragma unroll
        for (int j = 0; j < 8; j++)
            *(float4*)&g_h2[i * 64 + half * 32 + j * 4] = acc[j];
        float* asf = &as2v[half].x;
        float* adf = &ad2v[half].x;
#pragma unroll
        for (int h = 0; h < 4; h++) {
            int hd = half * 4 + h;
            float cs = 0.f, cd = 0.f;
#pragma unroll
            for (int c = 0; c < 8; c++) {
                float hv = accf[h * 8 + c];
                cs += hv * sAs[hd * 8 + c];
                cd += hv * sAd[hd * 8 + c];
            }
            asf[h] = cs;
            adf[h] = cd;
        }
    }
    *(float4*)&g_as2[i * 8]     = as2v[0];
    *(float4*)&g_as2[i * 8 + 4] = as2v[1];
    *(float4*)&g_ad2[i * 8]     = ad2v[0];
    *(float4*)&g_ad2[i * 8 + 4] = ad2v[1];
}

// ---------------- layer 2 gather + finalize + FC (warp per node) --------------
// lanes: slot = lane>>4 (2 edge slots), q = lane&15 -> channels q*4..q*4+3, head q>>1
__global__ void k_l2fc(const float* __restrict__ b2, const float* __restrict__ fcw,
                       const float* __restrict__ fcb, float* __restrict__ out, int N) {
    int gw = (blockIdx.x * blockDim.x + threadIdx.x) >> 5;
    if (gw >= N) return;
    int lane = threadIdx.x & 31;
    int slot = lane >> 4;
    int q = lane & 15;
    int ch = q * 4, hd = q >> 1;
    int start = g_off[gw], deg = g_deg[gw];
    float ad = g_ad2[gw * 8 + hd];
    float4 acc = make_float4(0.f, 0.f, 0.f, 0.f);
    float psum = 0.f;
    for (int k = slot; k < deg; k += 2) {
        int s = __ldg(&g_csr[start + k]);
        float as = __ldg(&g_as2[s * 8 + hd]);
        float p = __expf(lrelu(as + ad));
        float4 h = __ldg((const float4*)&g_h2[s * 64 + ch]);
        acc.x += p * h.x; acc.y += p * h.y;
        acc.z += p * h.z; acc.w += p * h.w;
        psum += p;
    }
    // combine the two edge slots (lanes differing in bit 4)
    acc.x += __shfl_xor_sync(0xffffffffu, acc.x, 16);
    acc.y += __shfl_xor_sync(0xffffffffu, acc.y, 16);
    acc.z += __shfl_xor_sync(0xffffffffu, acc.z, 16);
    acc.w += __shfl_xor_sync(0xffffffffu, acc.w, 16);
    psum  += __shfl_xor_sync(0xffffffffu, psum, 16);
    float inv = 1.f / (psum + EPS);
    float e0 = elu(acc.x * inv + __ldg(&b2[ch]));
    float e1 = elu(acc.y * inv + __ldg(&b2[ch + 1]));
    float e2 = elu(acc.z * inv + __ldg(&b2[ch + 2]));
    float e3 = elu(acc.w * inv + __ldg(&b2[ch + 3]));
    float part = e0 * __ldg(&fcw[ch])     + e1 * __ldg(&fcw[ch + 1])
               + e2 * __ldg(&fcw[ch + 2]) + e3 * __ldg(&fcw[ch + 3]);
    // reduce over the 16 channel-lanes (both halves hold identical data)
#pragma unroll
    for (int o = 8; o > 0; o >>= 1)
        part += __shfl_xor_sync(0xffffffffu, part, o);
    if (lane == 0) {
        out[gw] = part + __ldg(&fcb[0]);
        g_deg[gw] = 0;             // restore zero precondition for next call
    }
}

// ---------------- launch ------------------------------------------------------
extern "C" void kernel_launch(void* const* d_in, const int* in_sizes, int n_in,
                              void* d_out, int out_size) {
    const float* x    = (const float*)d_in[0];
    const int*   ei   = (const int*)  d_in[1];
    const float* W1   = (const float*)d_in[2];
    const float* as1  = (const float*)d_in[3];
    const float* ad1  = (const float*)d_in[4];
    const float* b1   = (const float*)d_in[5];
    const float* W2   = (const float*)d_in[6];
    const float* as2  = (const float*)d_in[7];
    const float* ad2  = (const float*)d_in[8];
    const float* b2   = (const float*)d_in[9];
    const float* fcw  = (const float*)d_in[10];
    const float* fcb  = (const float*)d_in[11];
    float* out = (float*)d_out;

    int N = in_sizes[0];          // x is [N, 1]
    int E = in_sizes[1] / 2;      // edge_index is [2, E]
    int Etot = E + N;             // + self loops
    const int* src = ei;
    const int* dst = ei + E;

    const int T = 256;
    k_l1n_hist <<<(E + T - 1) / T, T>>>(x, dst, W1, as1, ad1, N, E);
    k_scanA    <<<NSCANBLK, SCAN_BLK>>>(N);
    k_scanB    <<<1, 512>>>();
    k_scanC    <<<(N + T - 1) / T, T>>>(N);
    k_fill     <<<(Etot + T - 1) / T, T>>>(src, dst, E, Etot);
    k_l1_gather<<<(int)(((long)N * 32 + T - 1) / T), T>>>(x, N);
    k_mid      <<<(N + 127) / 128, 128>>>(W1, b1, W2, as2, ad2, N);
    k_l2fc     <<<(int)(((long)N * 32 + T - 1) / T), T>>>(b2, fcw, fcb, out, N);
}